// round 4
// baseline (speedup 1.0000x reference)
#include <cuda_runtime.h>
#include <cstdint>

#define E 128
#define L 64
#define NEG_INF -100000000.0f
#define MAX_B 8192
#define SROWS 32
#define MAX_PARTS (MAX_B / SROWS)

__device__ __align__(16) float g_feats[3ull * MAX_B * E];
__device__ float g_part[3 * MAX_PARTS];

__device__ __forceinline__ void cp_async16(void* smem_dst, const void* gsrc) {
    uint32_t s = (uint32_t)__cvta_generic_to_shared(smem_dst);
    asm volatile("cp.async.cg.shared.global [%0], [%1], 16;\n" :: "r"(s), "l"(gsrc));
}
__device__ __forceinline__ void cp_commit() { asm volatile("cp.async.commit_group;\n"); }
__device__ __forceinline__ void cp_wait0()  { asm volatile("cp.async.wait_group 0;\n"); }

// ---------------------------------------------------------------------------
// Fused branch kernel: grid (B, 3), 256 threads.
// Table-A rows register-resident; table-B rows streamed via cp.async -> smem.
// ---------------------------------------------------------------------------
__global__ __launch_bounds__(256) void branch_kernel(
    const float* __restrict__ user_embs, const float* __restrict__ item_embs,
    const float* __restrict__ w_uu, const float* __restrict__ w_uiu,
    const float* __restrict__ w_uui,
    const int* __restrict__ uid, const int* __restrict__ nbr,
    const int* __restrict__ uiu, const int* __restrict__ uui, int B)
{
    __shared__ int   s_idx[2 * L];
    __shared__ float s_self[E];
    __shared__ float s_whi[E];
    __shared__ float s_log[L];
    __shared__ float s_red[8];
    __shared__ float s_acc[8][E];
    __shared__ __align__(16) float tileB[L * E];   // 32 KB

    const int t    = threadIdx.x;
    const int wid  = t >> 5;
    const int lane = t & 31;
    const int b    = blockIdx.x;
    const int br   = blockIdx.y;

    const float* tabA; const float* tabB; const float* w;
    const int* idx; int stride; float scale; bool hasB;
    if (br == 0)      { tabA = user_embs; tabB = user_embs; w = w_uu;  idx = nbr; stride = L;     scale = 0.5f;    hasB = false; }
    else if (br == 1) { tabA = item_embs; tabB = user_embs; w = w_uiu; idx = uiu; stride = 2 * L; scale = 1.f/3.f; hasB = true; }
    else              { tabA = user_embs; tabB = item_embs; w = w_uui; idx = uui; stride = 2 * L; scale = 1.f/3.f; hasB = true; }

    // Phase 0: warps 0-3 load indices; warps 4-7 load self/w and do self-dots.
    if (t < stride) s_idx[t] = idx[(size_t)b * stride + t];
    if (t >= 128) {
        const int e = t - 128;
        const int u = uid[b];
        const float se  = user_embs[(size_t)u * E + e];
        const float wlo = w[e];
        const float whi = w[E + e];
        s_self[e] = se;
        s_whi[e]  = whi;
        float p0 = se * wlo, p1 = se * whi;
#pragma unroll
        for (int o = 16; o > 0; o >>= 1) {
            p0 += __shfl_xor_sync(0xffffffffu, p0, o);
            p1 += __shfl_xor_sync(0xffffffffu, p1, o);
        }
        if (lane == 0) { s_red[wid - 4] = p0; s_red[4 + (wid - 4)] = p1; }
    }
    __syncthreads();

    // Phase 1: gathers. B rows via cp.async into smem, A rows into registers.
    if (hasB) {
#pragma unroll
        for (int r = 0; r < 8; r++) {
            const int l = wid * 8 + r;
            cp_async16(&tileB[l * E + lane * 4],
                       tabB + (size_t)s_idx[L + l] * E + lane * 4);
        }
        cp_commit();
    }
    float4 rowA[8];
#pragma unroll
    for (int r = 0; r < 8; r++) {
        const int l = wid * 8 + r;
        rowA[r] = ((const float4*)(tabA + (size_t)s_idx[l] * E))[lane];
    }

    const float c_lo = s_red[0] + s_red[1] + s_red[2] + s_red[3];
    const float c_hi = s_red[4] + s_red[5] + s_red[6] + s_red[7];
    const float4 wh = ((const float4*)s_whi)[lane];

    if (hasB) cp_wait0();   // each lane re-reads only the 16B it copied

    // Phase 2: per-row logits
#pragma unroll
    for (int r = 0; r < 8; r++) {
        const int l = wid * 8 + r;
        float d = rowA[r].x * wh.x + rowA[r].y * wh.y +
                  rowA[r].z * wh.z + rowA[r].w * wh.w;
        if (hasB) {
            const float4 vb = ((const float4*)(tileB + l * E))[lane];
            d += vb.x * wh.x + vb.y * wh.y + vb.z * wh.z + vb.w * wh.w;
        }
#pragma unroll
        for (int o = 16; o > 0; o >>= 1) d += __shfl_xor_sync(0xffffffffu, d, o);
        if (lane == 0) {
            float x = c_lo + scale * (c_hi + d);
            x = (x > 0.f) ? x : 0.01f * x;
            if (s_idx[l] == 0) x += NEG_INF;
            s_log[l] = x;
        }
    }
    __syncthreads();

    // Phase 3: softmax over L=64 (warp 0)
    if (t < 32) {
        float v0 = s_log[t], v1 = s_log[t + 32];
        float m = fmaxf(v0, v1);
#pragma unroll
        for (int o = 16; o > 0; o >>= 1) m = fmaxf(m, __shfl_xor_sync(0xffffffffu, m, o));
        float e0 = expf(v0 - m), e1 = expf(v1 - m);
        float s = e0 + e1;
#pragma unroll
        for (int o = 16; o > 0; o >>= 1) s += __shfl_xor_sync(0xffffffffu, s, o);
        float inv = 1.f / s;
        s_log[t] = e0 * inv;
        s_log[t + 32] = e1 * inv;
    }
    __syncthreads();

    // Phase 4: weighted sum (A from regs, B from smem, own rows only)
    float4 acc = make_float4(0.f, 0.f, 0.f, 0.f);
#pragma unroll
    for (int r = 0; r < 8; r++) {
        const int l = wid * 8 + r;
        const float a = s_log[l];
        acc.x += a * rowA[r].x; acc.y += a * rowA[r].y;
        acc.z += a * rowA[r].z; acc.w += a * rowA[r].w;
        if (hasB) {
            const float4 vb = ((const float4*)(tileB + l * E))[lane];
            acc.x += a * vb.x; acc.y += a * vb.y;
            acc.z += a * vb.z; acc.w += a * vb.w;
        }
    }
    ((float4*)s_acc[wid])[lane] = acc;
    __syncthreads();

    // Phase 5: cross-warp reduce + store
    if (t < E) {
        float s = s_acc[0][t] + s_acc[1][t] + s_acc[2][t] + s_acc[3][t] +
                  s_acc[4][t] + s_acc[5][t] + s_acc[6][t] + s_acc[7][t];
        float f = scale * (s_self[t] + s);
        g_feats[((size_t)br * B + b) * E + t] = fmaxf(f, 0.f);
    }
}

// ---------------------------------------------------------------------------
// Scores: per-block partial of sum_b tanh(feat_b @ W0 + b0) . w1
// grid (B/SROWS, 3), 256 threads; each warp handles 4 rows (2 pairs).
// ---------------------------------------------------------------------------
__global__ __launch_bounds__(256) void scores_kernel(
    const float* __restrict__ W0, const float* __restrict__ b0,
    const float* __restrict__ w1, int B)
{
    __shared__ float sW0[E * 64];           // 32 KB
    __shared__ float sb0[64];
    __shared__ float sw1[64];
    __shared__ float sfeat[SROWS][E];       // 16 KB
    __shared__ float s_part[8];

    const int t = threadIdx.x;
    const int wid = t >> 5, lane = t & 31;
    for (int i = t; i < E * 64; i += 256) sW0[i] = W0[i];
    if (t < 64) { sb0[t] = b0[t]; sw1[t] = w1[t]; }

    const int br = blockIdx.y;
    const int base = blockIdx.x * SROWS;
    const float* fp = g_feats + ((size_t)br * B + base) * E;

    // Stage all 32 rows: each warp loads rows wid*4 .. wid*4+3
#pragma unroll
    for (int r = 0; r < 4; r++) {
        const int row = wid * 4 + r;
        ((float4*)sfeat[row])[lane] = ((const float4*)(fp + (size_t)row * E))[lane];
    }
    __syncthreads();

    float warp_sum = 0.f;
#pragma unroll
    for (int p = 0; p < 2; p++) {           // two row-pairs per warp
        const int r0 = wid * 4 + p * 2;
        float a00 = sb0[lane], a01 = sb0[lane + 32];
        float a10 = a00,       a11 = a01;
#pragma unroll
        for (int e = 0; e < E; e++) {
            const float w0a = sW0[e * 64 + lane];
            const float w0b = sW0[e * 64 + lane + 32];
            const float v0 = sfeat[r0][e];
            const float v1 = sfeat[r0 + 1][e];
            a00 += v0 * w0a; a01 += v0 * w0b;
            a10 += v1 * w0a; a11 += v1 * w0b;
        }
        warp_sum += (tanhf(a00) + tanhf(a10)) * sw1[lane] +
                    (tanhf(a01) + tanhf(a11)) * sw1[lane + 32];
    }
#pragma unroll
    for (int o = 16; o > 0; o >>= 1)
        warp_sum += __shfl_xor_sync(0xffffffffu, warp_sum, o);
    if (lane == 0) s_part[wid] = warp_sum;
    __syncthreads();
    if (t == 0) {
        g_part[br * MAX_PARTS + blockIdx.x] =
            s_part[0] + s_part[1] + s_part[2] + s_part[3] +
            s_part[4] + s_part[5] + s_part[6] + s_part[7];
    }
}

// ---------------------------------------------------------------------------
// Mix: inline score reduction (3 x nparts partials), then gated combine.
// One float4 per thread.
// ---------------------------------------------------------------------------
__global__ __launch_bounds__(256) void mix_kernel(
    float4* __restrict__ out, int B, int nparts)
{
    __shared__ float ssc[3];
    const int t = threadIdx.x, wid = t >> 5, lane = t & 31;

    if (wid < 3) {
        float v = 0.f;
        for (int i = lane; i < nparts; i += 32) v += g_part[wid * MAX_PARTS + i];
#pragma unroll
        for (int o = 16; o > 0; o >>= 1) v += __shfl_xor_sync(0xffffffffu, v, o);
        if (lane == 0) ssc[wid] = v;
    }
    __syncthreads();

    const float inv = 1.f / (float)B;
    const float s0 = ssc[0] * inv, s1 = ssc[1] * inv, s2 = ssc[2] * inv;
    const float m = fmaxf(s0, fmaxf(s1, s2));
    const float e0 = expf(s0 - m), e1 = expf(s1 - m), e2 = expf(s2 - m);
    const float d = 1.f / (e0 + e1 + e2);

    const int i = blockIdx.x * blockDim.x + t;
    const int total = B * E / 4;
    if (i >= total) return;
    const float4* f0 = (const float4*)g_feats;
    const float4* f1 = (const float4*)(g_feats + (size_t)B * E);
    const float4* f2 = (const float4*)(g_feats + (size_t)2 * B * E);
    float4 a = f0[i], b4 = f1[i], c = f2[i];
    float4 r;
    r.x = fmaxf((e0 * a.x + e1 * b4.x + e2 * c.x) * d, 0.f);
    r.y = fmaxf((e0 * a.y + e1 * b4.y + e2 * c.y) * d, 0.f);
    r.z = fmaxf((e0 * a.z + e1 * b4.z + e2 * c.z) * d, 0.f);
    r.w = fmaxf((e0 * a.w + e1 * b4.w + e2 * c.w) * d, 0.f);
    out[i] = r;
}

extern "C" void kernel_launch(void* const* d_in, const int* in_sizes, int n_in,
                              void* d_out, int out_size) {
    const float* user_embs = (const float*)d_in[0];
    const float* item_embs = (const float*)d_in[1];
    const float* w_uu  = (const float*)d_in[2];
    const float* w_uiu = (const float*)d_in[3];
    const float* w_uui = (const float*)d_in[4];
    const float* W0 = (const float*)d_in[5];
    const float* b0 = (const float*)d_in[6];
    const float* w1 = (const float*)d_in[7];
    const int* uid = (const int*)d_in[8];
    const int* nbr = (const int*)d_in[9];
    const int* uiu = (const int*)d_in[10];
    const int* uui = (const int*)d_in[11];
    float* out = (float*)d_out;

    const int B = in_sizes[8];

    dim3 g1(B, 3);
    branch_kernel<<<g1, 256>>>(user_embs, item_embs, w_uu, w_uiu, w_uui,
                               uid, nbr, uiu, uui, B);

    const int nparts = B / SROWS;
    dim3 g2(nparts, 3);
    scores_kernel<<<g2, 256>>>(W0, b0, w1, B);

    const int total4 = B * E / 4;
    mix_kernel<<<(total4 + 255) / 256, 256>>>((float4*)out, B, nparts);
}

// round 5
// speedup vs baseline: 1.1396x; 1.1396x over previous
#include <cuda_runtime.h>
#include <cstdint>

#define E 128
#define L 64
#define NEG_INF -100000000.0f
#define MAX_B 8192
#define SROWS 32
#define MAX_PARTS (MAX_B / SROWS)

__device__ __align__(16) float g_feats[3ull * MAX_B * E];
__device__ float g_part[3 * MAX_PARTS];

// ---------------------------------------------------------------------------
// Fused branch kernel: grid (B, 3), 256 threads (8 warps).
// One-pass online softmax: each warp streams its 8 neighbor rows from global
// exactly once; no smem tiles, tiny register payload.
// ---------------------------------------------------------------------------
__global__ __launch_bounds__(256) void branch_kernel(
    const float* __restrict__ user_embs, const float* __restrict__ item_embs,
    const float* __restrict__ w_uu, const float* __restrict__ w_uiu,
    const float* __restrict__ w_uui,
    const int* __restrict__ uid, const int* __restrict__ nbr,
    const int* __restrict__ uiu, const int* __restrict__ uui, int B)
{
    __shared__ int   s_idx[2 * L];
    __shared__ float s_self[E];
    __shared__ float s_whi[E];
    __shared__ float s_red[8];
    __shared__ float s_m[8];
    __shared__ float s_S[8];
    __shared__ float s_acc[8][E];

    const int t    = threadIdx.x;
    const int wid  = t >> 5;
    const int lane = t & 31;
    const int b    = blockIdx.x;
    const int br   = blockIdx.y;

    const float* tabA; const float* tabB; const float* w;
    const int* idx; int stride; float scale; bool hasB;
    if (br == 0)      { tabA = user_embs; tabB = user_embs; w = w_uu;  idx = nbr; stride = L;     scale = 0.5f;    hasB = false; }
    else if (br == 1) { tabA = item_embs; tabB = user_embs; w = w_uiu; idx = uiu; stride = 2 * L; scale = 1.f/3.f; hasB = true; }
    else              { tabA = user_embs; tabB = item_embs; w = w_uui; idx = uui; stride = 2 * L; scale = 1.f/3.f; hasB = true; }

    // Phase 0: warps 0-3 load indices; warps 4-7 load self/w and do self-dots.
    if (t < stride) s_idx[t] = idx[(size_t)b * stride + t];
    if (t >= 128) {
        const int e = t - 128;
        const int u = uid[b];
        const float se  = user_embs[(size_t)u * E + e];
        const float wlo = w[e];
        const float whi = w[E + e];
        s_self[e] = se;
        s_whi[e]  = whi;
        float p0 = se * wlo, p1 = se * whi;
#pragma unroll
        for (int o = 16; o > 0; o >>= 1) {
            p0 += __shfl_xor_sync(0xffffffffu, p0, o);
            p1 += __shfl_xor_sync(0xffffffffu, p1, o);
        }
        if (lane == 0) { s_red[wid - 4] = p0; s_red[4 + (wid - 4)] = p1; }
    }
    __syncthreads();

    const float c_lo = s_red[0] + s_red[1] + s_red[2] + s_red[3];
    const float c_hi = s_red[4] + s_red[5] + s_red[6] + s_red[7];
    const float4 wh = ((const float4*)s_whi)[lane];

    // Phase 1: one-pass online-softmax over this warp's 8 rows.
    float m = -3.0e38f, S = 0.f;
    float4 acc = make_float4(0.f, 0.f, 0.f, 0.f);

    // Prefetch row 0
    int l0 = wid * 8;
    float4 va = ((const float4*)(tabA + (size_t)s_idx[l0] * E))[lane];
    float4 vb = hasB ? ((const float4*)(tabB + (size_t)s_idx[L + l0] * E))[lane]
                     : make_float4(0.f, 0.f, 0.f, 0.f);

#pragma unroll
    for (int r = 0; r < 8; r++) {
        const int l = wid * 8 + r;
        // Prefetch next row while reducing current
        float4 va_n, vb_n;
        if (r < 7) {
            va_n = ((const float4*)(tabA + (size_t)s_idx[l + 1] * E))[lane];
            if (hasB)
                vb_n = ((const float4*)(tabB + (size_t)s_idx[L + l + 1] * E))[lane];
        }

        // Combined row (same softmax weight applies to va+vb)
        float4 vs;
        vs.x = va.x + vb.x; vs.y = va.y + vb.y;
        vs.z = va.z + vb.z; vs.w = va.w + vb.w;

        float d = vs.x * wh.x + vs.y * wh.y + vs.z * wh.z + vs.w * wh.w;
#pragma unroll
        for (int o = 16; o > 0; o >>= 1) d += __shfl_xor_sync(0xffffffffu, d, o);

        float x = c_lo + scale * (c_hi + d);
        x = (x > 0.f) ? x : 0.01f * x;          // leaky_relu
        if (s_idx[l] == 0) x += NEG_INF;        // mask

        const float mn = fmaxf(m, x);
        const float fo = expf(m - mn);          // first iter: exp(-huge) = 0
        const float e  = expf(x - mn);
        S = S * fo + e;
        acc.x = acc.x * fo + e * vs.x;
        acc.y = acc.y * fo + e * vs.y;
        acc.z = acc.z * fo + e * vs.z;
        acc.w = acc.w * fo + e * vs.w;
        m = mn;

        va = va_n; vb = hasB ? vb_n : make_float4(0.f, 0.f, 0.f, 0.f);
    }

    ((float4*)s_acc[wid])[lane] = acc;
    if (lane == 0) { s_m[wid] = m; s_S[wid] = S; }
    __syncthreads();

    // Phase 2: cross-warp merge + store (threads 0..127, one element each)
    if (t < E) {
        float M = s_m[0];
#pragma unroll
        for (int wI = 1; wI < 8; wI++) M = fmaxf(M, s_m[wI]);
        float T = 0.f, val = 0.f;
#pragma unroll
        for (int wI = 0; wI < 8; wI++) {
            const float g = expf(s_m[wI] - M);
            T   += s_S[wI] * g;
            val += g * s_acc[wI][t];
        }
        const float f = scale * (s_self[t] + val / T);
        g_feats[((size_t)br * B + b) * E + t] = fmaxf(f, 0.f);
    }
}

// ---------------------------------------------------------------------------
// Scores: per-block partial of sum_b tanh(feat_b @ W0 + b0) . w1
// ---------------------------------------------------------------------------
__global__ __launch_bounds__(256) void scores_kernel(
    const float* __restrict__ W0, const float* __restrict__ b0,
    const float* __restrict__ w1, int B)
{
    __shared__ float sW0[E * 64];
    __shared__ float sb0[64];
    __shared__ float sw1[64];
    __shared__ float sfeat[SROWS][E];
    __shared__ float s_part[8];

    const int t = threadIdx.x;
    const int wid = t >> 5, lane = t & 31;
    for (int i = t; i < E * 64; i += 256) sW0[i] = W0[i];
    if (t < 64) { sb0[t] = b0[t]; sw1[t] = w1[t]; }

    const int br = blockIdx.y;
    const int base = blockIdx.x * SROWS;
    const float* fp = g_feats + ((size_t)br * B + base) * E;

#pragma unroll
    for (int r = 0; r < 4; r++) {
        const int row = wid * 4 + r;
        ((float4*)sfeat[row])[lane] = ((const float4*)(fp + (size_t)row * E))[lane];
    }
    __syncthreads();

    float warp_sum = 0.f;
#pragma unroll
    for (int p = 0; p < 2; p++) {
        const int r0 = wid * 4 + p * 2;
        float a00 = sb0[lane], a01 = sb0[lane + 32];
        float a10 = a00,       a11 = a01;
#pragma unroll
        for (int e = 0; e < E; e++) {
            const float w0a = sW0[e * 64 + lane];
            const float w0b = sW0[e * 64 + lane + 32];
            const float v0 = sfeat[r0][e];
            const float v1 = sfeat[r0 + 1][e];
            a00 += v0 * w0a; a01 += v0 * w0b;
            a10 += v1 * w0a; a11 += v1 * w0b;
        }
        warp_sum += (tanhf(a00) + tanhf(a10)) * sw1[lane] +
                    (tanhf(a01) + tanhf(a11)) * sw1[lane + 32];
    }
#pragma unroll
    for (int o = 16; o > 0; o >>= 1)
        warp_sum += __shfl_xor_sync(0xffffffffu, warp_sum, o);
    if (lane == 0) s_part[wid] = warp_sum;
    __syncthreads();
    if (t == 0) {
        g_part[br * MAX_PARTS + blockIdx.x] =
            s_part[0] + s_part[1] + s_part[2] + s_part[3] +
            s_part[4] + s_part[5] + s_part[6] + s_part[7];
    }
}

// ---------------------------------------------------------------------------
// Mix: inline score reduction, then gated combine. One float4 per thread.
// ---------------------------------------------------------------------------
__global__ __launch_bounds__(256) void mix_kernel(
    float4* __restrict__ out, int B, int nparts)
{
    __shared__ float ssc[3];
    const int t = threadIdx.x, wid = t >> 5, lane = t & 31;

    if (wid < 3) {
        float v = 0.f;
        for (int i = lane; i < nparts; i += 32) v += g_part[wid * MAX_PARTS + i];
#pragma unroll
        for (int o = 16; o > 0; o >>= 1) v += __shfl_xor_sync(0xffffffffu, v, o);
        if (lane == 0) ssc[wid] = v;
    }
    __syncthreads();

    const float inv = 1.f / (float)B;
    const float s0 = ssc[0] * inv, s1 = ssc[1] * inv, s2 = ssc[2] * inv;
    const float m = fmaxf(s0, fmaxf(s1, s2));
    const float e0 = expf(s0 - m), e1 = expf(s1 - m), e2 = expf(s2 - m);
    const float d = 1.f / (e0 + e1 + e2);

    const int i = blockIdx.x * blockDim.x + t;
    const int total = B * E / 4;
    if (i >= total) return;
    const float4* f0 = (const float4*)g_feats;
    const float4* f1 = (const float4*)(g_feats + (size_t)B * E);
    const float4* f2 = (const float4*)(g_feats + (size_t)2 * B * E);
    float4 a = f0[i], b4 = f1[i], c = f2[i];
    float4 r;
    r.x = fmaxf((e0 * a.x + e1 * b4.x + e2 * c.x) * d, 0.f);
    r.y = fmaxf((e0 * a.y + e1 * b4.y + e2 * c.y) * d, 0.f);
    r.z = fmaxf((e0 * a.z + e1 * b4.z + e2 * c.z) * d, 0.f);
    r.w = fmaxf((e0 * a.w + e1 * b4.w + e2 * c.w) * d, 0.f);
    out[i] = r;
}

extern "C" void kernel_launch(void* const* d_in, const int* in_sizes, int n_in,
                              void* d_out, int out_size) {
    const float* user_embs = (const float*)d_in[0];
    const float* item_embs = (const float*)d_in[1];
    const float* w_uu  = (const float*)d_in[2];
    const float* w_uiu = (const float*)d_in[3];
    const float* w_uui = (const float*)d_in[4];
    const float* W0 = (const float*)d_in[5];
    const float* b0 = (const float*)d_in[6];
    const float* w1 = (const float*)d_in[7];
    const int* uid = (const int*)d_in[8];
    const int* nbr = (const int*)d_in[9];
    const int* uiu = (const int*)d_in[10];
    const int* uui = (const int*)d_in[11];
    float* out = (float*)d_out;

    const int B = in_sizes[8];

    dim3 g1(B, 3);
    branch_kernel<<<g1, 256>>>(user_embs, item_embs, w_uu, w_uiu, w_uui,
                               uid, nbr, uiu, uui, B);

    const int nparts = B / SROWS;
    dim3 g2(nparts, 3);
    scores_kernel<<<g2, 256>>>(W0, b0, w1, B);

    const int total4 = B * E / 4;
    mix_kernel<<<(total4 + 255) / 256, 256>>>((float4*)out, B, nparts);
}

// round 6
// speedup vs baseline: 1.2243x; 1.0743x over previous
#include <cuda_runtime.h>
#include <cstdint>

#define E 128
#define L 64
#define NEG_INF -100000000.0f
#define MAX_B 8192
#define SROWS 32
#define MAX_PARTS (MAX_B / SROWS)

__device__ __align__(16) float g_feats[3ull * MAX_B * E];
__device__ float g_part[3 * MAX_PARTS];

// ---------------------------------------------------------------------------
// Fused branch kernel: 256 threads (8 warps), one (b, br) per block.
// One-pass online softmax with warp-uniform branchy rescale + __expf.
// ---------------------------------------------------------------------------
template <bool HASB>
__global__ __launch_bounds__(256) void branch_kernel(
    const float* __restrict__ user_embs, const float* __restrict__ item_embs,
    const float* __restrict__ w_uiu, const float* __restrict__ w_uui,
    const int* __restrict__ uid, const int* __restrict__ idx0,
    const int* __restrict__ idx1, int B)
{
    __shared__ int   s_idx[2 * L];
    __shared__ float s_self[E];
    __shared__ float s_whi[E];
    __shared__ float s_red[8];
    __shared__ float s_m[8];
    __shared__ float s_S[8];
    __shared__ float s_acc[8][E];

    const int t    = threadIdx.x;
    const int wid  = t >> 5;
    const int lane = t & 31;
    const int b    = blockIdx.x;

    const float* tabA; const float* tabB; const float* w;
    const int* idx; int stride; float scale; int br;
    if (!HASB) {
        br = 0; tabA = user_embs; tabB = user_embs; w = w_uiu /*=w_uu here*/;
        idx = idx0; stride = L; scale = 0.5f;
    } else if (blockIdx.y == 0) {
        br = 1; tabA = item_embs; tabB = user_embs; w = w_uiu;
        idx = idx0; stride = 2 * L; scale = 1.f / 3.f;
    } else {
        br = 2; tabA = user_embs; tabB = item_embs; w = w_uui;
        idx = idx1; stride = 2 * L; scale = 1.f / 3.f;
    }

    // Phase 0: warps 0-3 load indices; warps 4-7 load self/w and do self-dots.
    if (t < stride) s_idx[t] = idx[(size_t)b * stride + t];
    if (t >= 128) {
        const int e = t - 128;
        const int u = uid[b];
        const float se  = user_embs[(size_t)u * E + e];
        const float wlo = w[e];
        const float whi = w[E + e];
        s_self[e] = se;
        s_whi[e]  = whi;
        float p0 = se * wlo, p1 = se * whi;
#pragma unroll
        for (int o = 16; o > 0; o >>= 1) {
            p0 += __shfl_xor_sync(0xffffffffu, p0, o);
            p1 += __shfl_xor_sync(0xffffffffu, p1, o);
        }
        if (lane == 0) { s_red[wid - 4] = p0; s_red[4 + (wid - 4)] = p1; }
    }
    __syncthreads();

    const float c_lo = s_red[0] + s_red[1] + s_red[2] + s_red[3];
    const float c_hi = s_red[4] + s_red[5] + s_red[6] + s_red[7];
    const float4 wh = ((const float4*)s_whi)[lane];

    // Phase 1: one-pass online softmax over this warp's 8 rows.
    float m = -3.0e38f, S = 0.f;
    float4 acc = make_float4(0.f, 0.f, 0.f, 0.f);

    const int l0 = wid * 8;
    float4 va = ((const float4*)(tabA + (size_t)s_idx[l0] * E))[lane];
    float4 vb;
    if (HASB) vb = ((const float4*)(tabB + (size_t)s_idx[L + l0] * E))[lane];

#pragma unroll
    for (int r = 0; r < 8; r++) {
        const int l = wid * 8 + r;

        float4 vs;
        if (HASB) {
            vs.x = va.x + vb.x; vs.y = va.y + vb.y;
            vs.z = va.z + vb.z; vs.w = va.w + vb.w;
        } else {
            vs = va;
        }

        // Prefetch next row
        if (r < 7) {
            va = ((const float4*)(tabA + (size_t)s_idx[l + 1] * E))[lane];
            if (HASB)
                vb = ((const float4*)(tabB + (size_t)s_idx[L + l + 1] * E))[lane];
        }

        float d = vs.x * wh.x + vs.y * wh.y + vs.z * wh.z + vs.w * wh.w;
#pragma unroll
        for (int o = 16; o > 0; o >>= 1) d += __shfl_xor_sync(0xffffffffu, d, o);

        float x = c_lo + scale * (c_hi + d);
        x = (x > 0.f) ? x : 0.01f * x;          // leaky_relu
        if (s_idx[l] == 0) x += NEG_INF;        // mask

        // Warp-uniform branch: x identical across lanes after butterfly.
        if (x > m) {
            const float fo = __expf(m - x);     // first iter: 0
            S = S * fo + 1.f;
            acc.x = acc.x * fo + vs.x;
            acc.y = acc.y * fo + vs.y;
            acc.z = acc.z * fo + vs.z;
            acc.w = acc.w * fo + vs.w;
            m = x;
        } else {
            const float e = __expf(x - m);
            S += e;
            acc.x += e * vs.x; acc.y += e * vs.y;
            acc.z += e * vs.z; acc.w += e * vs.w;
        }
    }

    ((float4*)s_acc[wid])[lane] = acc;
    if (lane == 0) { s_m[wid] = m; s_S[wid] = S; }
    __syncthreads();

    // Phase 2: cross-warp merge + store (threads 0..127, one element each)
    if (t < E) {
        float M = s_m[0];
#pragma unroll
        for (int wI = 1; wI < 8; wI++) M = fmaxf(M, s_m[wI]);
        float T = 0.f, val = 0.f;
#pragma unroll
        for (int wI = 0; wI < 8; wI++) {
            const float g = __expf(s_m[wI] - M);
            T   += s_S[wI] * g;
            val += g * s_acc[wI][t];
        }
        const float f = scale * (s_self[t] + val / T);
        g_feats[((size_t)br * B + b) * E + t] = fmaxf(f, 0.f);
    }
}

// ---------------------------------------------------------------------------
// Scores: per-block partial of sum_b tanh(feat_b @ W0 + b0) . w1
// ---------------------------------------------------------------------------
__global__ __launch_bounds__(256) void scores_kernel(
    const float* __restrict__ W0, const float* __restrict__ b0,
    const float* __restrict__ w1, int B)
{
    __shared__ float sW0[E * 64];
    __shared__ float sb0[64];
    __shared__ float sw1[64];
    __shared__ float sfeat[SROWS][E];
    __shared__ float s_part[8];

    const int t = threadIdx.x;
    const int wid = t >> 5, lane = t & 31;
    for (int i = t; i < E * 64; i += 256) sW0[i] = W0[i];
    if (t < 64) { sb0[t] = b0[t]; sw1[t] = w1[t]; }

    const int br = blockIdx.y;
    const int base = blockIdx.x * SROWS;
    const float* fp = g_feats + ((size_t)br * B + base) * E;

#pragma unroll
    for (int r = 0; r < 4; r++) {
        const int row = wid * 4 + r;
        ((float4*)sfeat[row])[lane] = ((const float4*)(fp + (size_t)row * E))[lane];
    }
    __syncthreads();

    float warp_sum = 0.f;
#pragma unroll
    for (int p = 0; p < 2; p++) {
        const int r0 = wid * 4 + p * 2;
        float a00 = sb0[lane], a01 = sb0[lane + 32];
        float a10 = a00,       a11 = a01;
#pragma unroll
        for (int e = 0; e < E; e++) {
            const float w0a = sW0[e * 64 + lane];
            const float w0b = sW0[e * 64 + lane + 32];
            const float v0 = sfeat[r0][e];
            const float v1 = sfeat[r0 + 1][e];
            a00 += v0 * w0a; a01 += v0 * w0b;
            a10 += v1 * w0a; a11 += v1 * w0b;
        }
        warp_sum += (tanhf(a00) + tanhf(a10)) * sw1[lane] +
                    (tanhf(a01) + tanhf(a11)) * sw1[lane + 32];
    }
#pragma unroll
    for (int o = 16; o > 0; o >>= 1)
        warp_sum += __shfl_xor_sync(0xffffffffu, warp_sum, o);
    if (lane == 0) s_part[wid] = warp_sum;
    __syncthreads();
    if (t == 0) {
        g_part[br * MAX_PARTS + blockIdx.x] =
            s_part[0] + s_part[1] + s_part[2] + s_part[3] +
            s_part[4] + s_part[5] + s_part[6] + s_part[7];
    }
}

// ---------------------------------------------------------------------------
// Mix: inline score reduction, then gated combine. One float4 per thread.
// ---------------------------------------------------------------------------
__global__ __launch_bounds__(256) void mix_kernel(
    float4* __restrict__ out, int B, int nparts)
{
    __shared__ float ssc[3];
    const int t = threadIdx.x, wid = t >> 5, lane = t & 31;

    if (wid < 3) {
        float v = 0.f;
        for (int i = lane; i < nparts; i += 32) v += g_part[wid * MAX_PARTS + i];
#pragma unroll
        for (int o = 16; o > 0; o >>= 1) v += __shfl_xor_sync(0xffffffffu, v, o);
        if (lane == 0) ssc[wid] = v;
    }
    __syncthreads();

    const float inv = 1.f / (float)B;
    const float s0 = ssc[0] * inv, s1 = ssc[1] * inv, s2 = ssc[2] * inv;
    const float m = fmaxf(s0, fmaxf(s1, s2));
    const float e0 = expf(s0 - m), e1 = expf(s1 - m), e2 = expf(s2 - m);
    const float d = 1.f / (e0 + e1 + e2);

    const int i = blockIdx.x * blockDim.x + t;
    const int total = B * E / 4;
    if (i >= total) return;
    const float4* f0 = (const float4*)g_feats;
    const float4* f1 = (const float4*)(g_feats + (size_t)B * E);
    const float4* f2 = (const float4*)(g_feats + (size_t)2 * B * E);
    float4 a = f0[i], b4 = f1[i], c = f2[i];
    float4 r;
    r.x = fmaxf((e0 * a.x + e1 * b4.x + e2 * c.x) * d, 0.f);
    r.y = fmaxf((e0 * a.y + e1 * b4.y + e2 * c.y) * d, 0.f);
    r.z = fmaxf((e0 * a.z + e1 * b4.z + e2 * c.z) * d, 0.f);
    r.w = fmaxf((e0 * a.w + e1 * b4.w + e2 * c.w) * d, 0.f);
    out[i] = r;
}

extern "C" void kernel_launch(void* const* d_in, const int* in_sizes, int n_in,
                              void* d_out, int out_size) {
    const float* user_embs = (const float*)d_in[0];
    const float* item_embs = (const float*)d_in[1];
    const float* w_uu  = (const float*)d_in[2];
    const float* w_uiu = (const float*)d_in[3];
    const float* w_uui = (const float*)d_in[4];
    const float* W0 = (const float*)d_in[5];
    const float* b0 = (const float*)d_in[6];
    const float* w1 = (const float*)d_in[7];
    const int* uid = (const int*)d_in[8];
    const int* nbr = (const int*)d_in[9];
    const int* uiu = (const int*)d_in[10];
    const int* uui = (const int*)d_in[11];
    float* out = (float*)d_out;

    const int B = in_sizes[8];

    // Branch 0 (uu): no table B
    branch_kernel<false><<<dim3(B, 1), 256>>>(
        user_embs, item_embs, w_uu, w_uu, uid, nbr, nbr, B);
    // Branches 1,2 (uiu, uui)
    branch_kernel<true><<<dim3(B, 2), 256>>>(
        user_embs, item_embs, w_uiu, w_uui, uid, uiu, uui, B);

    const int nparts = B / SROWS;
    dim3 g2(nparts, 3);
    scores_kernel<<<g2, 256>>>(W0, b0, w1, B);

    const int total4 = B * E / 4;
    mix_kernel<<<(total4 + 255) / 256, 256>>>((float4*)out, B, nparts);
}

// round 7
// speedup vs baseline: 1.2522x; 1.0228x over previous
#include <cuda_runtime.h>
#include <cstdint>

#define E 128
#define L 64
#define NEG_INF -100000000.0f
#define MAX_B 8192
#define SROWS 32
#define MAX_PARTS (MAX_B / SROWS)

__device__ __align__(16) float g_feats[3ull * MAX_B * E];
__device__ float g_part[3 * MAX_PARTS];

// ---------------------------------------------------------------------------
// Fused branch kernel: 256 threads (8 warps), one (b, br) per block.
// Batched softmax: 8 rows register-resident, independent dot butterflies,
// single max, 8 independent __expf, weighted sum from registers.
// ---------------------------------------------------------------------------
template <bool HASB>
__global__ __launch_bounds__(256, 4) void branch_kernel(
    const float* __restrict__ user_embs, const float* __restrict__ item_embs,
    const float* __restrict__ w_uiu, const float* __restrict__ w_uui,
    const int* __restrict__ uid, const int* __restrict__ idx0,
    const int* __restrict__ idx1, int B)
{
    __shared__ int   s_idx[2 * L];
    __shared__ float s_self[E];
    __shared__ float s_whi[E];
    __shared__ float s_red[8];
    __shared__ float s_m[8];
    __shared__ float s_S[8];
    __shared__ float s_acc[8][E];

    const int t    = threadIdx.x;
    const int wid  = t >> 5;
    const int lane = t & 31;
    const int b    = blockIdx.x;

    const float* tabA; const float* tabB; const float* w;
    const int* idx; int stride; float scale; int br;
    if (!HASB) {
        br = 0; tabA = user_embs; tabB = user_embs; w = w_uiu /* = w_uu */;
        idx = idx0; stride = L; scale = 0.5f;
    } else if (blockIdx.y == 0) {
        br = 1; tabA = item_embs; tabB = user_embs; w = w_uiu;
        idx = idx0; stride = 2 * L; scale = 1.f / 3.f;
    } else {
        br = 2; tabA = user_embs; tabB = item_embs; w = w_uui;
        idx = idx1; stride = 2 * L; scale = 1.f / 3.f;
    }

    // Phase 0: warps 0-3 load indices; warps 4-7 load self/w and do self-dots.
    if (t < stride) s_idx[t] = idx[(size_t)b * stride + t];
    if (t >= 128) {
        const int e = t - 128;
        const int u = uid[b];
        const float se  = user_embs[(size_t)u * E + e];
        const float wlo = w[e];
        const float whi = w[E + e];
        s_self[e] = se;
        s_whi[e]  = whi;
        float p0 = se * wlo, p1 = se * whi;
#pragma unroll
        for (int o = 16; o > 0; o >>= 1) {
            p0 += __shfl_xor_sync(0xffffffffu, p0, o);
            p1 += __shfl_xor_sync(0xffffffffu, p1, o);
        }
        if (lane == 0) { s_red[wid - 4] = p0; s_red[4 + (wid - 4)] = p1; }
    }
    __syncthreads();

    const float c_lo = s_red[0] + s_red[1] + s_red[2] + s_red[3];
    const float c_hi = s_red[4] + s_red[5] + s_red[6] + s_red[7];
    const float4 wh = ((const float4*)s_whi)[lane];

    // Phase 1: load this warp's 8 rows into registers, compute dot partials.
    float4 vs[8];
    float  d[8];
#pragma unroll
    for (int r = 0; r < 8; r++) {
        const int l = wid * 8 + r;
        float4 va = ((const float4*)(tabA + (size_t)s_idx[l] * E))[lane];
        if (HASB) {
            const float4 vb = ((const float4*)(tabB + (size_t)s_idx[L + l] * E))[lane];
            va.x += vb.x; va.y += vb.y; va.z += vb.z; va.w += vb.w;
        }
        vs[r] = va;
        d[r] = va.x * wh.x + va.y * wh.y + va.z * wh.z + va.w * wh.w;
    }

    // Phase 2: 8 independent butterfly reductions (pipelined).
#pragma unroll
    for (int o = 16; o > 0; o >>= 1) {
#pragma unroll
        for (int r = 0; r < 8; r++)
            d[r] += __shfl_xor_sync(0xffffffffu, d[r], o);
    }

    // Phase 3: logits (warp-uniform), max, exp, weighted sum.
    float m = -3.0e38f;
#pragma unroll
    for (int r = 0; r < 8; r++) {
        float x = c_lo + scale * (c_hi + d[r]);
        x = (x > 0.f) ? x : 0.01f * x;               // leaky_relu
        if (s_idx[wid * 8 + r] == 0) x += NEG_INF;   // mask
        d[r] = x;
        m = fmaxf(m, x);
    }
    float S = 0.f;
    float4 acc = make_float4(0.f, 0.f, 0.f, 0.f);
#pragma unroll
    for (int r = 0; r < 8; r++) {
        const float e = __expf(d[r] - m);
        S += e;
        acc.x += e * vs[r].x; acc.y += e * vs[r].y;
        acc.z += e * vs[r].z; acc.w += e * vs[r].w;
    }

    ((float4*)s_acc[wid])[lane] = acc;
    if (lane == 0) { s_m[wid] = m; s_S[wid] = S; }
    __syncthreads();

    // Phase 4: cross-warp merge + store (threads 0..127, one element each)
    if (t < E) {
        float M = s_m[0];
#pragma unroll
        for (int wI = 1; wI < 8; wI++) M = fmaxf(M, s_m[wI]);
        float T = 0.f, val = 0.f;
#pragma unroll
        for (int wI = 0; wI < 8; wI++) {
            const float g = __expf(s_m[wI] - M);
            T   += s_S[wI] * g;
            val += g * s_acc[wI][t];
        }
        const float f = scale * (s_self[t] + val / T);
        g_feats[((size_t)br * B + b) * E + t] = fmaxf(f, 0.f);
    }
}

// ---------------------------------------------------------------------------
// Scores: per-block partial of sum_b tanh(feat_b @ W0 + b0) . w1
// ---------------------------------------------------------------------------
__global__ __launch_bounds__(256) void scores_kernel(
    const float* __restrict__ W0, const float* __restrict__ b0,
    const float* __restrict__ w1, int B)
{
    __shared__ float sW0[E * 64];
    __shared__ float sb0[64];
    __shared__ float sw1[64];
    __shared__ float sfeat[SROWS][E];
    __shared__ float s_part[8];

    const int t = threadIdx.x;
    const int wid = t >> 5, lane = t & 31;
    for (int i = t; i < E * 64; i += 256) sW0[i] = W0[i];
    if (t < 64) { sb0[t] = b0[t]; sw1[t] = w1[t]; }

    const int br = blockIdx.y;
    const int base = blockIdx.x * SROWS;
    const float* fp = g_feats + ((size_t)br * B + base) * E;

#pragma unroll
    for (int r = 0; r < 4; r++) {
        const int row = wid * 4 + r;
        ((float4*)sfeat[row])[lane] = ((const float4*)(fp + (size_t)row * E))[lane];
    }
    __syncthreads();

    float warp_sum = 0.f;
#pragma unroll
    for (int p = 0; p < 2; p++) {
        const int r0 = wid * 4 + p * 2;
        float a00 = sb0[lane], a01 = sb0[lane + 32];
        float a10 = a00,       a11 = a01;
#pragma unroll
        for (int e = 0; e < E; e++) {
            const float w0a = sW0[e * 64 + lane];
            const float w0b = sW0[e * 64 + lane + 32];
            const float v0 = sfeat[r0][e];
            const float v1 = sfeat[r0 + 1][e];
            a00 += v0 * w0a; a01 += v0 * w0b;
            a10 += v1 * w0a; a11 += v1 * w0b;
        }
        warp_sum += (tanhf(a00) + tanhf(a10)) * sw1[lane] +
                    (tanhf(a01) + tanhf(a11)) * sw1[lane + 32];
    }
#pragma unroll
    for (int o = 16; o > 0; o >>= 1)
        warp_sum += __shfl_xor_sync(0xffffffffu, warp_sum, o);
    if (lane == 0) s_part[wid] = warp_sum;
    __syncthreads();
    if (t == 0) {
        g_part[br * MAX_PARTS + blockIdx.x] =
            s_part[0] + s_part[1] + s_part[2] + s_part[3] +
            s_part[4] + s_part[5] + s_part[6] + s_part[7];
    }
}

// ---------------------------------------------------------------------------
// Mix: inline score reduction, then gated combine. One float4 per thread.
// ---------------------------------------------------------------------------
__global__ __launch_bounds__(256) void mix_kernel(
    float4* __restrict__ out, int B, int nparts)
{
    __shared__ float ssc[3];
    const int t = threadIdx.x, wid = t >> 5, lane = t & 31;

    if (wid < 3) {
        float v = 0.f;
        for (int i = lane; i < nparts; i += 32) v += g_part[wid * MAX_PARTS + i];
#pragma unroll
        for (int o = 16; o > 0; o >>= 1) v += __shfl_xor_sync(0xffffffffu, v, o);
        if (lane == 0) ssc[wid] = v;
    }
    __syncthreads();

    const float inv = 1.f / (float)B;
    const float s0 = ssc[0] * inv, s1 = ssc[1] * inv, s2 = ssc[2] * inv;
    const float m = fmaxf(s0, fmaxf(s1, s2));
    const float e0 = expf(s0 - m), e1 = expf(s1 - m), e2 = expf(s2 - m);
    const float d = 1.f / (e0 + e1 + e2);

    const int i = blockIdx.x * blockDim.x + t;
    const int total = B * E / 4;
    if (i >= total) return;
    const float4* f0 = (const float4*)g_feats;
    const float4* f1 = (const float4*)(g_feats + (size_t)B * E);
    const float4* f2 = (const float4*)(g_feats + (size_t)2 * B * E);
    float4 a = f0[i], b4 = f1[i], c = f2[i];
    float4 r;
    r.x = fmaxf((e0 * a.x + e1 * b4.x + e2 * c.x) * d, 0.f);
    r.y = fmaxf((e0 * a.y + e1 * b4.y + e2 * c.y) * d, 0.f);
    r.z = fmaxf((e0 * a.z + e1 * b4.z + e2 * c.z) * d, 0.f);
    r.w = fmaxf((e0 * a.w + e1 * b4.w + e2 * c.w) * d, 0.f);
    out[i] = r;
}

extern "C" void kernel_launch(void* const* d_in, const int* in_sizes, int n_in,
                              void* d_out, int out_size) {
    const float* user_embs = (const float*)d_in[0];
    const float* item_embs = (const float*)d_in[1];
    const float* w_uu  = (const float*)d_in[2];
    const float* w_uiu = (const float*)d_in[3];
    const float* w_uui = (const float*)d_in[4];
    const float* W0 = (const float*)d_in[5];
    const float* b0 = (const float*)d_in[6];
    const float* w1 = (const float*)d_in[7];
    const int* uid = (const int*)d_in[8];
    const int* nbr = (const int*)d_in[9];
    const int* uiu = (const int*)d_in[10];
    const int* uui = (const int*)d_in[11];
    float* out = (float*)d_out;

    const int B = in_sizes[8];

    // Branch 0 (uu): no table B
    branch_kernel<false><<<dim3(B, 1), 256>>>(
        user_embs, item_embs, w_uu, w_uu, uid, nbr, nbr, B);
    // Branches 1,2 (uiu, uui)
    branch_kernel<true><<<dim3(B, 2), 256>>>(
        user_embs, item_embs, w_uiu, w_uui, uid, uiu, uui, B);

    const int nparts = B / SROWS;
    dim3 g2(nparts, 3);
    scores_kernel<<<g2, 256>>>(W0, b0, w1, B);

    const int total4 = B * E / 4;
    mix_kernel<<<(total4 + 255) / 256, 256>>>((float4*)out, B, nparts);
}

// round 9
// speedup vs baseline: 1.3639x; 1.0892x over previous
#include <cuda_runtime.h>
#include <cstdint>

#define E 128
#define L 64
#define MAX_B 8192
#define SROWS 32
#define MAX_PARTS (MAX_B / SROWS)

__device__ __align__(16) float g_feats[3ull * MAX_B * E];
__device__ float g_part[3 * MAX_PARTS];

__device__ __forceinline__ float warp_sum32(float v) {
#pragma unroll
    for (int o = 16; o > 0; o >>= 1) v += __shfl_xor_sync(0xffffffffu, v, o);
    return v;
}

// ---------------------------------------------------------------------------
// Fused branch kernel: 256 threads (8 warps), one (b, br) per block.
// Pairing-tree reduction of 8 dots (9 shuffles), one exp per lane,
// unstabilized softmax with exact-0 masked weights.
// ---------------------------------------------------------------------------
template <bool HASB>
__global__ __launch_bounds__(256, 4) void branch_kernel(
    const float* __restrict__ user_embs, const float* __restrict__ item_embs,
    const float* __restrict__ w_uiu, const float* __restrict__ w_uui,
    const int* __restrict__ uid, const int* __restrict__ idx0,
    const int* __restrict__ idx1, int B)
{
    __shared__ int   s_idx[2 * L];
    __shared__ float s_self[E];
    __shared__ float s_whi[E];
    __shared__ float s_red[8];
    __shared__ float s_S[8];
    __shared__ float s_acc[8][E];

    const int t    = threadIdx.x;
    const int wid  = t >> 5;
    const int lane = t & 31;
    const int b    = blockIdx.x;

    const float* tabA; const float* tabB; const float* w;
    const int* idx; int stride; float scale; int br;
    if (!HASB) {
        br = 0; tabA = user_embs; tabB = user_embs; w = w_uiu /* = w_uu */;
        idx = idx0; stride = L; scale = 0.5f;
    } else if (blockIdx.y == 0) {
        br = 1; tabA = item_embs; tabB = user_embs; w = w_uiu;
        idx = idx0; stride = 2 * L; scale = 1.f / 3.f;
    } else {
        br = 2; tabA = user_embs; tabB = item_embs; w = w_uui;
        idx = idx1; stride = 2 * L; scale = 1.f / 3.f;
    }

    // Phase 0: warps 0-3 load indices; warps 4-7 load self/w + self-dots.
    if (t < stride) s_idx[t] = idx[(size_t)b * stride + t];
    if (t >= 128) {
        const int e = t - 128;
        const int u = uid[b];
        const float se  = user_embs[(size_t)u * E + e];
        const float wlo = w[e];
        const float whi = w[E + e];
        s_self[e] = se;
        s_whi[e]  = whi;
        const float p0 = warp_sum32(se * wlo);
        const float p1 = warp_sum32(se * whi);
        if (lane == 0) { s_red[wid - 4] = p0; s_red[4 + (wid - 4)] = p1; }
    }
    __syncthreads();

    const float c_lo = s_red[0] + s_red[1] + s_red[2] + s_red[3];
    const float c_hi = s_red[4] + s_red[5] + s_red[6] + s_red[7];
    const float4 wh = ((const float4*)s_whi)[lane];

    // Phase 1: load this warp's 8 rows into registers + dot partials.
    int ia[8];
#pragma unroll
    for (int r = 0; r < 8; r++) ia[r] = s_idx[wid * 8 + r];

    float4 vs[8];
    float  d[8];
#pragma unroll
    for (int r = 0; r < 8; r++) {
        float4 va = ((const float4*)(tabA + (size_t)ia[r] * E))[lane];
        if (HASB) {
            const int ib = s_idx[L + wid * 8 + r];
            const float4 vb = ((const float4*)(tabB + (size_t)ib * E))[lane];
            va.x += vb.x; va.y += vb.y; va.z += vb.z; va.w += vb.w;
        }
        vs[r] = va;
        d[r] = va.x * wh.x + va.y * wh.y + va.z * wh.z + va.w * wh.w;
    }

    // Phase 2: pairing-tree reduction. After this, lane i holds the FULL dot
    // of row  r(i) = 4*bit2(i) + 2*bit3(i) + bit4(i).
    const bool b4 = lane & 16, b3 = lane & 8, b2 = lane & 4;
    float x4[4];
#pragma unroll
    for (int r = 0; r < 4; r++) {
        const float keep = b4 ? d[2 * r + 1] : d[2 * r];
        const float send = b4 ? d[2 * r]     : d[2 * r + 1];
        x4[r] = keep + __shfl_xor_sync(0xffffffffu, send, 16);
    }
    float z2[2];
#pragma unroll
    for (int r = 0; r < 2; r++) {
        const float keep = b3 ? x4[2 * r + 1] : x4[2 * r];
        const float send = b3 ? x4[2 * r]     : x4[2 * r + 1];
        z2[r] = keep + __shfl_xor_sync(0xffffffffu, send, 8);
    }
    float v = (b2 ? z2[1] : z2[0]) +
              __shfl_xor_sync(0xffffffffu, b2 ? z2[0] : z2[1], 4);
    v += __shfl_xor_sync(0xffffffffu, v, 2);
    v += __shfl_xor_sync(0xffffffffu, v, 1);

    // Phase 3: one logit + exp per lane for its row; masked rows -> 0.
    const int myrow = (b2 ? 4 : 0) + (b3 ? 2 : 0) + (b4 ? 1 : 0);
    const int myidx = s_idx[wid * 8 + myrow];
    float xl = c_lo + scale * (c_hi + v);
    xl = (xl > 0.f) ? xl : 0.01f * xl;              // leaky_relu
    const float e_mine = (myidx == 0) ? 0.f : __expf(xl);

    // Broadcast: row r lives in lane src(r) = ((r&1)<<4)|((r&2)<<2)|(r&4).
    float eb[8];
#pragma unroll
    for (int r = 0; r < 8; r++) {
        const int src = ((r & 1) << 4) | ((r & 2) << 2) | (r & 4);
        eb[r] = __shfl_sync(0xffffffffu, e_mine, src);
    }

    float S = 0.f;
    float4 acc = make_float4(0.f, 0.f, 0.f, 0.f);
#pragma unroll
    for (int r = 0; r < 8; r++) {
        const float e = eb[r];
        S += e;
        acc.x += e * vs[r].x; acc.y += e * vs[r].y;
        acc.z += e * vs[r].z; acc.w += e * vs[r].w;
    }

    ((float4*)s_acc[wid])[lane] = acc;
    if (lane == 0) s_S[wid] = S;
    __syncthreads();

    // Phase 4: plain cross-warp sum + store (threads 0..127).
    if (t < E) {
        const float T = s_S[0] + s_S[1] + s_S[2] + s_S[3] +
                        s_S[4] + s_S[5] + s_S[6] + s_S[7];
        const float val = s_acc[0][t] + s_acc[1][t] + s_acc[2][t] + s_acc[3][t] +
                          s_acc[4][t] + s_acc[5][t] + s_acc[6][t] + s_acc[7][t];
        const float f = scale * (s_self[t] + val / T);
        g_feats[((size_t)br * B + b) * E + t] = fmaxf(f, 0.f);
    }
}

// ---------------------------------------------------------------------------
// Scores: per-block partial of sum_b tanh(feat_b @ W0 + b0) . w1
// ---------------------------------------------------------------------------
__global__ __launch_bounds__(256) void scores_kernel(
    const float* __restrict__ W0, const float* __restrict__ b0,
    const float* __restrict__ w1, int B)
{
    __shared__ float sW0[E * 64];
    __shared__ float sb0[64];
    __shared__ float sw1[64];
    __shared__ float sfeat[SROWS][E];
    __shared__ float s_part[8];

    const int t = threadIdx.x;
    const int wid = t >> 5, lane = t & 31;
    for (int i = t; i < E * 64; i += 256) sW0[i] = W0[i];
    if (t < 64) { sb0[t] = b0[t]; sw1[t] = w1[t]; }

    const int br = blockIdx.y;
    const int base = blockIdx.x * SROWS;
    const float* fp = g_feats + ((size_t)br * B + base) * E;

#pragma unroll
    for (int r = 0; r < 4; r++) {
        const int row = wid * 4 + r;
        ((float4*)sfeat[row])[lane] = ((const float4*)(fp + (size_t)row * E))[lane];
    }
    __syncthreads();

    float warp_sum = 0.f;
#pragma unroll
    for (int p = 0; p < 2; p++) {
        const int r0 = wid * 4 + p * 2;
        float a00 = sb0[lane], a01 = sb0[lane + 32];
        float a10 = a00,       a11 = a01;
#pragma unroll
        for (int e = 0; e < E; e++) {
            const float w0a = sW0[e * 64 + lane];
            const float w0b = sW0[e * 64 + lane + 32];
            const float v0 = sfeat[r0][e];
            const float v1 = sfeat[r0 + 1][e];
            a00 += v0 * w0a; a01 += v0 * w0b;
            a10 += v1 * w0a; a11 += v1 * w0b;
        }
        warp_sum += (tanhf(a00) + tanhf(a10)) * sw1[lane] +
                    (tanhf(a01) + tanhf(a11)) * sw1[lane + 32];
    }
    warp_sum = warp_sum32(warp_sum);
    if (lane == 0) s_part[wid] = warp_sum;
    __syncthreads();
    if (t == 0) {
        g_part[br * MAX_PARTS + blockIdx.x] =
            s_part[0] + s_part[1] + s_part[2] + s_part[3] +
            s_part[4] + s_part[5] + s_part[6] + s_part[7];
    }
}

// ---------------------------------------------------------------------------
// Mix: inline score reduction, then gated combine. One float4 per thread.
// ---------------------------------------------------------------------------
__global__ __launch_bounds__(256) void mix_kernel(
    float4* __restrict__ out, int B, int nparts)
{
    __shared__ float ssc[3];
    const int t = threadIdx.x, wid = t >> 5, lane = t & 31;

    if (wid < 3) {
        float v = 0.f;
        for (int i = lane; i < nparts; i += 32) v += g_part[wid * MAX_PARTS + i];
        v = warp_sum32(v);
        if (lane == 0) ssc[wid] = v;
    }
    __syncthreads();

    const float inv = 1.f / (float)B;
    const float s0 = ssc[0] * inv, s1 = ssc[1] * inv, s2 = ssc[2] * inv;
    const float m = fmaxf(s0, fmaxf(s1, s2));
    const float e0 = expf(s0 - m), e1 = expf(s1 - m), e2 = expf(s2 - m);
    const float d = 1.f / (e0 + e1 + e2);

    const int i = blockIdx.x * blockDim.x + t;
    const int total = B * E / 4;
    if (i >= total) return;
    const float4* f0 = (const float4*)g_feats;
    const float4* f1 = (const float4*)(g_feats + (size_t)B * E);
    const float4* f2 = (const float4*)(g_feats + (size_t)2 * B * E);
    float4 a = f0[i], b4 = f1[i], c = f2[i];
    float4 r;
    r.x = fmaxf((e0 * a.x + e1 * b4.x + e2 * c.x) * d, 0.f);
    r.y = fmaxf((e0 * a.y + e1 * b4.y + e2 * c.y) * d, 0.f);
    r.z = fmaxf((e0 * a.z + e1 * b4.z + e2 * c.z) * d, 0.f);
    r.w = fmaxf((e0 * a.w + e1 * b4.w + e2 * c.w) * d, 0.f);
    out[i] = r;
}

extern "C" void kernel_launch(void* const* d_in, const int* in_sizes, int n_in,
                              void* d_out, int out_size) {
    const float* user_embs = (const float*)d_in[0];
    const float* item_embs = (const float*)d_in[1];
    const float* w_uu  = (const float*)d_in[2];
    const float* w_uiu = (const float*)d_in[3];
    const float* w_uui = (const float*)d_in[4];
    const float* W0 = (const float*)d_in[5];
    const float* b0 = (const float*)d_in[6];
    const float* w1 = (const float*)d_in[7];
    const int* uid = (const int*)d_in[8];
    const int* nbr = (const int*)d_in[9];
    const int* uiu = (const int*)d_in[10];
    const int* uui = (const int*)d_in[11];
    float* out = (float*)d_out;

    const int B = in_sizes[8];

    // Branch 0 (uu): no table B
    branch_kernel<false><<<dim3(B, 1), 256>>>(
        user_embs, item_embs, w_uu, w_uu, uid, nbr, nbr, B);
    // Branches 1,2 (uiu, uui)
    branch_kernel<true><<<dim3(B, 2), 256>>>(
        user_embs, item_embs, w_uiu, w_uui, uid, uiu, uui, B);

    const int nparts = B / SROWS;
    dim3 g2(nparts, 3);
    scores_kernel<<<g2, 256>>>(W0, b0, w1, B);

    const int total4 = B * E / 4;
    mix_kernel<<<(total4 + 255) / 256, 256>>>((float4*)out, B, nparts);
}

// round 10
// speedup vs baseline: 1.4057x; 1.0306x over previous
#include <cuda_runtime.h>
#include <cstdint>

#define E 128
#define L 64
#define MAX_B 8192
#define SROWS 32
#define MAX_PARTS (MAX_B / SROWS)

typedef unsigned long long ull;

__device__ __align__(16) float g_feats[3ull * MAX_B * E];
__device__ float g_part[3 * MAX_PARTS];

__device__ __forceinline__ float warp_sum32(float v) {
#pragma unroll
    for (int o = 16; o > 0; o >>= 1) v += __shfl_xor_sync(0xffffffffu, v, o);
    return v;
}

// ---- Blackwell packed f32x2 ops (SASS FFMA2/FADD2, PTX-only) ----
__device__ __forceinline__ ull fma2(ull a, ull b, ull c) {
    ull r; asm("fma.rn.f32x2 %0, %1, %2, %3;" : "=l"(r) : "l"(a), "l"(b), "l"(c));
    return r;
}
__device__ __forceinline__ ull add2(ull a, ull b) {
    ull r; asm("add.rn.f32x2 %0, %1, %2;" : "=l"(r) : "l"(a), "l"(b));
    return r;
}
__device__ __forceinline__ ull mul2(ull a, ull b) {
    ull r; asm("mul.rn.f32x2 %0, %1, %2;" : "=l"(r) : "l"(a), "l"(b));
    return r;
}
__device__ __forceinline__ float2 unpack2(ull v) {
    float2 f; asm("mov.b64 {%0, %1}, %2;" : "=f"(f.x), "=f"(f.y) : "l"(v));
    return f;
}
__device__ __forceinline__ ull pack2(float a, float b) {
    ull r; asm("mov.b64 %0, {%1, %2};" : "=l"(r) : "f"(a), "f"(b));
    return r;
}

// ---------------------------------------------------------------------------
// Fused branch kernel: 256 threads (8 warps), one (b, br) per block.
// Packed f32x2 elementwise math; pairing-tree dot reduction (9 shuffles);
// one exp per lane; unstabilized softmax with exact-0 masked weights.
// ---------------------------------------------------------------------------
template <bool HASB>
__global__ __launch_bounds__(256, 4) void branch_kernel(
    const float* __restrict__ user_embs, const float* __restrict__ item_embs,
    const float* __restrict__ w_uiu, const float* __restrict__ w_uui,
    const int* __restrict__ uid, const int* __restrict__ idx0,
    const int* __restrict__ idx1, int B)
{
    __shared__ int   s_idx[2 * L];
    __shared__ float s_self[E];
    __shared__ __align__(16) float s_whi[E];
    __shared__ float s_red[8];
    __shared__ float s_S[8];
    __shared__ __align__(16) float s_acc[8][E];

    const int t    = threadIdx.x;
    const int wid  = t >> 5;
    const int lane = t & 31;
    const int b    = blockIdx.x;

    const float* tabA; const float* tabB; const float* w;
    const int* idx; int stride; float scale; int br;
    if (!HASB) {
        br = 0; tabA = user_embs; tabB = user_embs; w = w_uiu /* = w_uu */;
        idx = idx0; stride = L; scale = 0.5f;
    } else if (blockIdx.y == 0) {
        br = 1; tabA = item_embs; tabB = user_embs; w = w_uiu;
        idx = idx0; stride = 2 * L; scale = 1.f / 3.f;
    } else {
        br = 2; tabA = user_embs; tabB = item_embs; w = w_uui;
        idx = idx1; stride = 2 * L; scale = 1.f / 3.f;
    }

    // Phase 0: warps 0-3 load indices; warps 4-7 load self/w + self-dots.
    if (t < stride) s_idx[t] = idx[(size_t)b * stride + t];
    if (t >= 128) {
        const int e = t - 128;
        const int u = uid[b];
        const float se  = user_embs[(size_t)u * E + e];
        const float wlo = w[e];
        const float whi = w[E + e];
        s_self[e] = se;
        s_whi[e]  = whi;
        const float p0 = warp_sum32(se * wlo);
        const float p1 = warp_sum32(se * whi);
        if (lane == 0) { s_red[wid - 4] = p0; s_red[4 + (wid - 4)] = p1; }
    }
    __syncthreads();

    const float c_lo = s_red[0] + s_red[1] + s_red[2] + s_red[3];
    const float c_hi = s_red[4] + s_red[5] + s_red[6] + s_red[7];
    const ulonglong2 wh2 = ((const ulonglong2*)s_whi)[lane];

    // Phase 1: load this warp's 8 rows (packed pairs) + dot partials.
    int ia[8];
#pragma unroll
    for (int r = 0; r < 8; r++) ia[r] = s_idx[wid * 8 + r];

    ulonglong2 vs[8];
    float d[8];
#pragma unroll
    for (int r = 0; r < 8; r++) {
        ulonglong2 va = ((const ulonglong2*)(tabA + (size_t)ia[r] * E))[lane];
        if (HASB) {
            const int ib = s_idx[L + wid * 8 + r];
            const ulonglong2 vb = ((const ulonglong2*)(tabB + (size_t)ib * E))[lane];
            va.x = add2(va.x, vb.x);
            va.y = add2(va.y, vb.y);
        }
        vs[r] = va;
        const ull d2 = fma2(va.y, wh2.y, mul2(va.x, wh2.x));
        const float2 dd = unpack2(d2);
        d[r] = dd.x + dd.y;
    }

    // Phase 2: pairing-tree reduction. After this, lane i holds the FULL dot
    // of row  r(i) = 4*bit2(i) + 2*bit3(i) + bit4(i).
    const bool b4 = lane & 16, b3 = lane & 8, b2 = lane & 4;
    float x4[4];
#pragma unroll
    for (int r = 0; r < 4; r++) {
        const float keep = b4 ? d[2 * r + 1] : d[2 * r];
        const float send = b4 ? d[2 * r]     : d[2 * r + 1];
        x4[r] = keep + __shfl_xor_sync(0xffffffffu, send, 16);
    }
    float z2[2];
#pragma unroll
    for (int r = 0; r < 2; r++) {
        const float keep = b3 ? x4[2 * r + 1] : x4[2 * r];
        const float send = b3 ? x4[2 * r]     : x4[2 * r + 1];
        z2[r] = keep + __shfl_xor_sync(0xffffffffu, send, 8);
    }
    float v = (b2 ? z2[1] : z2[0]) +
              __shfl_xor_sync(0xffffffffu, b2 ? z2[0] : z2[1], 4);
    v += __shfl_xor_sync(0xffffffffu, v, 2);
    v += __shfl_xor_sync(0xffffffffu, v, 1);

    // Phase 3: one logit + exp per lane for its row; masked rows -> 0.
    const int myrow = (b2 ? 4 : 0) + (b3 ? 2 : 0) + (b4 ? 1 : 0);
    const int myidx = s_idx[wid * 8 + myrow];
    float xl = c_lo + scale * (c_hi + v);
    xl = (xl > 0.f) ? xl : 0.01f * xl;              // leaky_relu
    const float e_mine = (myidx == 0) ? 0.f : __expf(xl);

    // Broadcast: row r lives in lane src(r) = ((r&1)<<4)|((r&2)<<2)|(r&4).
    float S = 0.f;
    ulonglong2 acc; acc.x = 0ull; acc.y = 0ull;
#pragma unroll
    for (int r = 0; r < 8; r++) {
        const int src = ((r & 1) << 4) | ((r & 2) << 2) | (r & 4);
        const float e = __shfl_sync(0xffffffffu, e_mine, src);
        S += e;
        const ull e2 = pack2(e, e);
        acc.x = fma2(e2, vs[r].x, acc.x);
        acc.y = fma2(e2, vs[r].y, acc.y);
    }

    ((ulonglong2*)s_acc[wid])[lane] = acc;
    if (lane == 0) s_S[wid] = S;
    __syncthreads();

    // Phase 4: plain cross-warp sum + store (threads 0..127).
    if (t < E) {
        const float T = s_S[0] + s_S[1] + s_S[2] + s_S[3] +
                        s_S[4] + s_S[5] + s_S[6] + s_S[7];
        const float val = s_acc[0][t] + s_acc[1][t] + s_acc[2][t] + s_acc[3][t] +
                          s_acc[4][t] + s_acc[5][t] + s_acc[6][t] + s_acc[7][t];
        const float f = scale * (s_self[t] + val / T);
        g_feats[((size_t)br * B + b) * E + t] = fmaxf(f, 0.f);
    }
}

// ---------------------------------------------------------------------------
// Scores: per-block partial of sum_b tanh(feat_b @ W0 + b0) . w1
// ---------------------------------------------------------------------------
__global__ __launch_bounds__(256) void scores_kernel(
    const float* __restrict__ W0, const float* __restrict__ b0,
    const float* __restrict__ w1, int B)
{
    __shared__ float sW0[E * 64];
    __shared__ float sb0[64];
    __shared__ float sw1[64];
    __shared__ float sfeat[SROWS][E];
    __shared__ float s_part[8];

    const int t = threadIdx.x;
    const int wid = t >> 5, lane = t & 31;
    for (int i = t; i < E * 64; i += 256) sW0[i] = W0[i];
    if (t < 64) { sb0[t] = b0[t]; sw1[t] = w1[t]; }

    const int br = blockIdx.y;
    const int base = blockIdx.x * SROWS;
    const float* fp = g_feats + ((size_t)br * B + base) * E;

#pragma unroll
    for (int r = 0; r < 4; r++) {
        const int row = wid * 4 + r;
        ((float4*)sfeat[row])[lane] = ((const float4*)(fp + (size_t)row * E))[lane];
    }
    __syncthreads();

    float warp_sum = 0.f;
#pragma unroll
    for (int p = 0; p < 2; p++) {
        const int r0 = wid * 4 + p * 2;
        float a00 = sb0[lane], a01 = sb0[lane + 32];
        float a10 = a00,       a11 = a01;
#pragma unroll
        for (int e = 0; e < E; e++) {
            const float w0a = sW0[e * 64 + lane];
            const float w0b = sW0[e * 64 + lane + 32];
            const float v0 = sfeat[r0][e];
            const float v1 = sfeat[r0 + 1][e];
            a00 += v0 * w0a; a01 += v0 * w0b;
            a10 += v1 * w0a; a11 += v1 * w0b;
        }
        warp_sum += (tanhf(a00) + tanhf(a10)) * sw1[lane] +
                    (tanhf(a01) + tanhf(a11)) * sw1[lane + 32];
    }
    warp_sum = warp_sum32(warp_sum);
    if (lane == 0) s_part[wid] = warp_sum;
    __syncthreads();
    if (t == 0) {
        g_part[br * MAX_PARTS + blockIdx.x] =
            s_part[0] + s_part[1] + s_part[2] + s_part[3] +
            s_part[4] + s_part[5] + s_part[6] + s_part[7];
    }
}

// ---------------------------------------------------------------------------
// Mix: inline score reduction, then gated combine. One float4 per thread.
// ---------------------------------------------------------------------------
__global__ __launch_bounds__(256) void mix_kernel(
    float4* __restrict__ out, int B, int nparts)
{
    __shared__ float ssc[3];
    const int t = threadIdx.x, wid = t >> 5, lane = t & 31;

    if (wid < 3) {
        float v = 0.f;
        for (int i = lane; i < nparts; i += 32) v += g_part[wid * MAX_PARTS + i];
        v = warp_sum32(v);
        if (lane == 0) ssc[wid] = v;
    }
    __syncthreads();

    const float inv = 1.f / (float)B;
    const float s0 = ssc[0] * inv, s1 = ssc[1] * inv, s2 = ssc[2] * inv;
    const float m = fmaxf(s0, fmaxf(s1, s2));
    const float e0 = expf(s0 - m), e1 = expf(s1 - m), e2 = expf(s2 - m);
    const float d = 1.f / (e0 + e1 + e2);

    const int i = blockIdx.x * blockDim.x + t;
    const int total = B * E / 4;
    if (i >= total) return;
    const float4* f0 = (const float4*)g_feats;
    const float4* f1 = (const float4*)(g_feats + (size_t)B * E);
    const float4* f2 = (const float4*)(g_feats + (size_t)2 * B * E);
    float4 a = f0[i], b4 = f1[i], c = f2[i];
    float4 r;
    r.x = fmaxf((e0 * a.x + e1 * b4.x + e2 * c.x) * d, 0.f);
    r.y = fmaxf((e0 * a.y + e1 * b4.y + e2 * c.y) * d, 0.f);
    r.z = fmaxf((e0 * a.z + e1 * b4.z + e2 * c.z) * d, 0.f);
    r.w = fmaxf((e0 * a.w + e1 * b4.w + e2 * c.w) * d, 0.f);
    out[i] = r;
}

extern "C" void kernel_launch(void* const* d_in, const int* in_sizes, int n_in,
                              void* d_out, int out_size) {
    const float* user_embs = (const float*)d_in[0];
    const float* item_embs = (const float*)d_in[1];
    const float* w_uu  = (const float*)d_in[2];
    const float* w_uiu = (const float*)d_in[3];
    const float* w_uui = (const float*)d_in[4];
    const float* W0 = (const float*)d_in[5];
    const float* b0 = (const float*)d_in[6];
    const float* w1 = (const float*)d_in[7];
    const int* uid = (const int*)d_in[8];
    const int* nbr = (const int*)d_in[9];
    const int* uiu = (const int*)d_in[10];
    const int* uui = (const int*)d_in[11];
    float* out = (float*)d_out;

    const int B = in_sizes[8];

    // Branch 0 (uu): no table B
    branch_kernel<false><<<dim3(B, 1), 256>>>(
        user_embs, item_embs, w_uu, w_uu, uid, nbr, nbr, B);
    // Branches 1,2 (uiu, uui)
    branch_kernel<true><<<dim3(B, 2), 256>>>(
        user_embs, item_embs, w_uiu, w_uui, uid, uiu, uui, B);

    const int nparts = B / SROWS;
    dim3 g2(nparts, 3);
    scores_kernel<<<g2, 256>>>(W0, b0, w1, B);

    const int total4 = B * E / 4;
    mix_kernel<<<(total4 + 255) / 256, 256>>>((float4*)out, B, nparts);
}

// round 11
// speedup vs baseline: 1.4387x; 1.0234x over previous
#include <cuda_runtime.h>
#include <cstdint>

#define E 128
#define L 64
#define MAX_B 8192
#define SROWS 32
#define MAX_PARTS (MAX_B / SROWS)

typedef unsigned long long ull;

__device__ __align__(16) float g_feats[3ull * MAX_B * E];
__device__ __align__(16) float g_part[3 * MAX_PARTS];

__device__ __forceinline__ float warp_sum32(float v) {
#pragma unroll
    for (int o = 16; o > 0; o >>= 1) v += __shfl_xor_sync(0xffffffffu, v, o);
    return v;
}

// ---- Blackwell packed f32x2 ops (SASS FFMA2/FADD2, PTX-only) ----
__device__ __forceinline__ ull fma2(ull a, ull b, ull c) {
    ull r; asm("fma.rn.f32x2 %0, %1, %2, %3;" : "=l"(r) : "l"(a), "l"(b), "l"(c));
    return r;
}
__device__ __forceinline__ ull add2(ull a, ull b) {
    ull r; asm("add.rn.f32x2 %0, %1, %2;" : "=l"(r) : "l"(a), "l"(b));
    return r;
}
__device__ __forceinline__ ull mul2(ull a, ull b) {
    ull r; asm("mul.rn.f32x2 %0, %1, %2;" : "=l"(r) : "l"(a), "l"(b));
    return r;
}
__device__ __forceinline__ float2 unpack2(ull v) {
    float2 f; asm("mov.b64 {%0, %1}, %2;" : "=f"(f.x), "=f"(f.y) : "l"(v));
    return f;
}
__device__ __forceinline__ ull pack2(float a, float b) {
    ull r; asm("mov.b64 %0, {%1, %2};" : "=l"(r) : "f"(a), "f"(b));
    return r;
}

// ---------------------------------------------------------------------------
// Fused branch kernel: grid (B, 3), 256 threads, runtime branch dispatch.
// Packed f32x2 math; pairing-tree dot reduction; one exp per lane;
// unstabilized softmax with exact-0 masked weights.
// ---------------------------------------------------------------------------
__global__ __launch_bounds__(256, 4) void branch_kernel(
    const float* __restrict__ user_embs, const float* __restrict__ item_embs,
    const float* __restrict__ w_uu, const float* __restrict__ w_uiu,
    const float* __restrict__ w_uui,
    const int* __restrict__ uid, const int* __restrict__ nbr,
    const int* __restrict__ uiu, const int* __restrict__ uui, int B)
{
    __shared__ int   s_idx[2 * L];
    __shared__ float s_self[E];
    __shared__ __align__(16) float s_whi[E];
    __shared__ float s_red[8];
    __shared__ float s_S[8];
    __shared__ __align__(16) float s_acc[8][E];

    const int t    = threadIdx.x;
    const int wid  = t >> 5;
    const int lane = t & 31;
    const int b    = blockIdx.x;
    const int br   = blockIdx.y;
    const bool hasB = (br != 0);

    const float* tabA; const float* tabB; const float* w;
    const int* idx; int stride; float scale;
    if (br == 0)      { tabA = user_embs; tabB = user_embs; w = w_uu;  idx = nbr; stride = L;     scale = 0.5f;    }
    else if (br == 1) { tabA = item_embs; tabB = user_embs; w = w_uiu; idx = uiu; stride = 2 * L; scale = 1.f/3.f; }
    else              { tabA = user_embs; tabB = item_embs; w = w_uui; idx = uui; stride = 2 * L; scale = 1.f/3.f; }

    // Phase 0: warps 0-3 load indices; warps 4-7 load self/w + self-dots.
    if (t < stride) s_idx[t] = idx[(size_t)b * stride + t];
    if (t >= 128) {
        const int e = t - 128;
        const int u = uid[b];
        const float se  = user_embs[(size_t)u * E + e];
        const float wlo = w[e];
        const float whi = w[E + e];
        s_self[e] = se;
        s_whi[e]  = whi;
        const float p0 = warp_sum32(se * wlo);
        const float p1 = warp_sum32(se * whi);
        if (lane == 0) { s_red[wid - 4] = p0; s_red[4 + (wid - 4)] = p1; }
    }
    __syncthreads();

    const float c_lo = s_red[0] + s_red[1] + s_red[2] + s_red[3];
    const float c_hi = s_red[4] + s_red[5] + s_red[6] + s_red[7];
    const ulonglong2 wh2 = ((const ulonglong2*)s_whi)[lane];

    // Phase 1: load this warp's 8 rows (packed pairs) + dot partials.
    int ia[8];
#pragma unroll
    for (int r = 0; r < 8; r++) ia[r] = s_idx[wid * 8 + r];

    ulonglong2 vs[8];
    float d[8];
#pragma unroll
    for (int r = 0; r < 8; r++) {
        ulonglong2 va = ((const ulonglong2*)(tabA + (size_t)ia[r] * E))[lane];
        if (hasB) {
            const int ib = s_idx[L + wid * 8 + r];
            const ulonglong2 vb = ((const ulonglong2*)(tabB + (size_t)ib * E))[lane];
            va.x = add2(va.x, vb.x);
            va.y = add2(va.y, vb.y);
        }
        vs[r] = va;
        const ull d2 = fma2(va.y, wh2.y, mul2(va.x, wh2.x));
        const float2 dd = unpack2(d2);
        d[r] = dd.x + dd.y;
    }

    // Phase 2: pairing-tree reduction. After this, lane i holds the FULL dot
    // of row  r(i) = 4*bit2(i) + 2*bit3(i) + bit4(i).
    const bool b4 = lane & 16, b3 = lane & 8, b2 = lane & 4;
    float x4[4];
#pragma unroll
    for (int r = 0; r < 4; r++) {
        const float keep = b4 ? d[2 * r + 1] : d[2 * r];
        const float send = b4 ? d[2 * r]     : d[2 * r + 1];
        x4[r] = keep + __shfl_xor_sync(0xffffffffu, send, 16);
    }
    float z2[2];
#pragma unroll
    for (int r = 0; r < 2; r++) {
        const float keep = b3 ? x4[2 * r + 1] : x4[2 * r];
        const float send = b3 ? x4[2 * r]     : x4[2 * r + 1];
        z2[r] = keep + __shfl_xor_sync(0xffffffffu, send, 8);
    }
    float v = (b2 ? z2[1] : z2[0]) +
              __shfl_xor_sync(0xffffffffu, b2 ? z2[0] : z2[1], 4);
    v += __shfl_xor_sync(0xffffffffu, v, 2);
    v += __shfl_xor_sync(0xffffffffu, v, 1);

    // Phase 3: one logit + exp per lane for its row; masked rows -> 0.
    const int myrow = (b2 ? 4 : 0) + (b3 ? 2 : 0) + (b4 ? 1 : 0);
    const int myidx = s_idx[wid * 8 + myrow];
    float xl = c_lo + scale * (c_hi + v);
    xl = (xl > 0.f) ? xl : 0.01f * xl;              // leaky_relu
    const float e_mine = (myidx == 0) ? 0.f : __expf(xl);

    // Broadcast: row r lives in lane src(r) = ((r&1)<<4)|((r&2)<<2)|(r&4).
    float S = 0.f;
    ulonglong2 acc; acc.x = 0ull; acc.y = 0ull;
#pragma unroll
    for (int r = 0; r < 8; r++) {
        const int src = ((r & 1) << 4) | ((r & 2) << 2) | (r & 4);
        const float e = __shfl_sync(0xffffffffu, e_mine, src);
        S += e;
        const ull e2 = pack2(e, e);
        acc.x = fma2(e2, vs[r].x, acc.x);
        acc.y = fma2(e2, vs[r].y, acc.y);
    }

    ((ulonglong2*)s_acc[wid])[lane] = acc;
    if (lane == 0) s_S[wid] = S;
    __syncthreads();

    // Phase 4: plain cross-warp sum + store (threads 0..127).
    if (t < E) {
        const float T = s_S[0] + s_S[1] + s_S[2] + s_S[3] +
                        s_S[4] + s_S[5] + s_S[6] + s_S[7];
        const float val = s_acc[0][t] + s_acc[1][t] + s_acc[2][t] + s_acc[3][t] +
                          s_acc[4][t] + s_acc[5][t] + s_acc[6][t] + s_acc[7][t];
        const float f = scale * (s_self[t] + val / T);
        g_feats[((size_t)br * B + b) * E + t] = fmaxf(f, 0.f);
    }
}

// ---------------------------------------------------------------------------
// Scores: per-block partial of sum_b tanh(feat_b @ W0 + b0) . w1
// ---------------------------------------------------------------------------
__global__ __launch_bounds__(256) void scores_kernel(
    const float* __restrict__ W0, const float* __restrict__ b0,
    const float* __restrict__ w1, int B)
{
    __shared__ float sW0[E * 64];
    __shared__ float sb0[64];
    __shared__ float sw1[64];
    __shared__ float sfeat[SROWS][E];
    __shared__ float s_part[8];

    const int t = threadIdx.x;
    const int wid = t >> 5, lane = t & 31;

    const int br = blockIdx.y;
    const int base = blockIdx.x * SROWS;
    const float* fp = g_feats + ((size_t)br * B + base) * E;

#pragma unroll
    for (int r = 0; r < 4; r++) {
        const int row = wid * 4 + r;
        ((float4*)sfeat[row])[lane] = ((const float4*)(fp + (size_t)row * E))[lane];
    }
    for (int i = t; i < E * 64; i += 256) sW0[i] = W0[i];
    if (t < 64) { sb0[t] = b0[t]; sw1[t] = w1[t]; }
    __syncthreads();

    float warp_sum = 0.f;
#pragma unroll
    for (int p = 0; p < 2; p++) {
        const int r0 = wid * 4 + p * 2;
        float a00 = sb0[lane], a01 = sb0[lane + 32];
        float a10 = a00,       a11 = a01;
#pragma unroll
        for (int e = 0; e < E; e++) {
            const float w0a = sW0[e * 64 + lane];
            const float w0b = sW0[e * 64 + lane + 32];
            const float v0 = sfeat[r0][e];
            const float v1 = sfeat[r0 + 1][e];
            a00 += v0 * w0a; a01 += v0 * w0b;
            a10 += v1 * w0a; a11 += v1 * w0b;
        }
        warp_sum += (tanhf(a00) + tanhf(a10)) * sw1[lane] +
                    (tanhf(a01) + tanhf(a11)) * sw1[lane + 32];
    }
    warp_sum = warp_sum32(warp_sum);
    if (lane == 0) s_part[wid] = warp_sum;
    __syncthreads();
    if (t == 0) {
        g_part[br * MAX_PARTS + blockIdx.x] =
            s_part[0] + s_part[1] + s_part[2] + s_part[3] +
            s_part[4] + s_part[5] + s_part[6] + s_part[7];
    }
}

// ---------------------------------------------------------------------------
// Mix: gather loads issued FIRST, gate reduction overlapped, then combine.
// ---------------------------------------------------------------------------
__global__ __launch_bounds__(256) void mix_kernel(
    float4* __restrict__ out, int B, int nparts)
{
    __shared__ float ssc[3];
    const int t = threadIdx.x, wid = t >> 5, lane = t & 31;

    const int i = blockIdx.x * blockDim.x + t;
    const int total = B * E / 4;
    const bool valid = (i < total);

    // Issue long-latency gathers first.
    float4 a, b4v, c;
    if (valid) {
        a   = ((const float4*)g_feats)[i];
        b4v = ((const float4*)(g_feats + (size_t)B * E))[i];
        c   = ((const float4*)(g_feats + (size_t)2 * B * E))[i];
    }

    // Gate reduction while gathers are in flight (warps 0-2).
    if (wid < 3) {
        float v = 0.f;
        if ((nparts & 3) == 0) {
            const float4* gp = (const float4*)(g_part + wid * MAX_PARTS);
            for (int j = lane; j * 4 < nparts; j += 32) {
                const float4 p = gp[j];
                v += (p.x + p.y) + (p.z + p.w);
            }
        } else {
            for (int j = lane; j < nparts; j += 32)
                v += g_part[wid * MAX_PARTS + j];
        }
        v = warp_sum32(v);
        if (lane == 0) ssc[wid] = v;
    }
    __syncthreads();

    const float inv = 1.f / (float)B;
    const float s0 = ssc[0] * inv, s1 = ssc[1] * inv, s2 = ssc[2] * inv;
    const float m = fmaxf(s0, fmaxf(s1, s2));
    const float e0 = expf(s0 - m), e1 = expf(s1 - m), e2 = expf(s2 - m);
    const float dd = 1.f / (e0 + e1 + e2);

    if (!valid) return;
    float4 r;
    r.x = fmaxf((e0 * a.x + e1 * b4v.x + e2 * c.x) * dd, 0.f);
    r.y = fmaxf((e0 * a.y + e1 * b4v.y + e2 * c.y) * dd, 0.f);
    r.z = fmaxf((e0 * a.z + e1 * b4v.z + e2 * c.z) * dd, 0.f);
    r.w = fmaxf((e0 * a.w + e1 * b4v.w + e2 * c.w) * dd, 0.f);
    out[i] = r;
}

extern "C" void kernel_launch(void* const* d_in, const int* in_sizes, int n_in,
                              void* d_out, int out_size) {
    const float* user_embs = (const float*)d_in[0];
    const float* item_embs = (const float*)d_in[1];
    const float* w_uu  = (const float*)d_in[2];
    const float* w_uiu = (const float*)d_in[3];
    const float* w_uui = (const float*)d_in[4];
    const float* W0 = (const float*)d_in[5];
    const float* b0 = (const float*)d_in[6];
    const float* w1 = (const float*)d_in[7];
    const int* uid = (const int*)d_in[8];
    const int* nbr = (const int*)d_in[9];
    const int* uiu = (const int*)d_in[10];
    const int* uui = (const int*)d_in[11];
    float* out = (float*)d_out;

    const int B = in_sizes[8];

    // All three branches in ONE launch: light and heavy blocks interleave.
    branch_kernel<<<dim3(B, 3), 256>>>(user_embs, item_embs, w_uu, w_uiu, w_uui,
                                       uid, nbr, uiu, uui, B);

    const int nparts = B / SROWS;
    dim3 g2(nparts, 3);
    scores_kernel<<<g2, 256>>>(W0, b0, w1, B);

    const int total4 = B * E / 4;
    mix_kernel<<<(total4 + 255) / 256, 256>>>((float4*)out, B, nparts);
}